// round 15
// baseline (speedup 1.0000x reference)
#include <cuda_runtime.h>
#include <cuda_bf16.h>
#include <math.h>
#include <stdint.h>

#define Bdim 8192
#define Ddim 64
#define Odim 256

// ---------------- global scratch ----------------
__device__ __align__(16) __nv_bfloat16 g_xs2[2 * Bdim * Ddim];          // [split][b][d]
__device__ __align__(16) __nv_bfloat16 g_bs2[Odim * 2 * Ddim * Ddim];   // [o][split][e][d]
__device__ float g_cproj[Odim * Ddim];

// ---------------- helpers ----------------
__device__ __forceinline__ unsigned smem_u32(const void* p) {
    unsigned a;
    asm("{ .reg .u64 t; cvta.to.shared.u64 t, %1; cvt.u32.u64 %0, t; }" : "=r"(a) : "l"(p));
    return a;
}
__device__ __forceinline__ void split2(float a, __nv_bfloat16& h, __nv_bfloat16& l) {
    h = __float2bfloat16(a);
    l = __float2bfloat16(a - __bfloat162float(h));
}
__device__ __forceinline__ void ldsm4(unsigned* r, unsigned addr) {
    asm volatile("ldmatrix.sync.aligned.m8n8.x4.shared.b16 {%0,%1,%2,%3}, [%4];"
                 : "=r"(r[0]), "=r"(r[1]), "=r"(r[2]), "=r"(r[3]) : "r"(addr));
}
__device__ __forceinline__ void mma16816(float* c, const unsigned* a, const unsigned* b) {
    asm volatile("mma.sync.aligned.m16n8k16.row.col.f32.bf16.bf16.f32 "
                 "{%0,%1,%2,%3}, {%4,%5,%6,%7}, {%8,%9}, {%0,%1,%2,%3};"
                 : "+f"(c[0]), "+f"(c[1]), "+f"(c[2]), "+f"(c[3])
                 : "r"(a[0]), "r"(a[1]), "r"(a[2]), "r"(a[3]), "r"(b[0]), "r"(b[1]));
}
#define CP_ASYNC16(dst, src) \
    asm volatile("cp.async.cg.shared.global [%0], [%1], 16;" :: "r"(dst), "l"(src) : "memory")
#define CP_COMMIT() asm volatile("cp.async.commit_group;" ::: "memory")
#define CP_WAIT1()  asm volatile("cp.async.wait_group 1;" ::: "memory")
#define CP_WAIT0()  asm volatile("cp.async.wait_group 0;" ::: "memory")

// ---------------- merged prep kernel ----------------
// blocks [0, 1024): x split ; blocks [1024, 1280): beta split + cproj
__global__ __launch_bounds__(256) void prep_kernel(const float* __restrict__ x,
                                                   const float* __restrict__ betas,
                                                   const float* __restrict__ centers) {
    __shared__ float bsm[Ddim * Ddim];
    __shared__ float cs[Ddim];
    int t = threadIdx.x;

    if (blockIdx.x < 1024) {
        int idx = blockIdx.x * 256 + t;          // 262144 = 8192*32
        int b = idx >> 5, dp = idx & 31;
        float2 v = *(const float2*)(x + b * Ddim + 2 * dp);
        __nv_bfloat16 h0, l0, h1, l1;
        split2(v.x, h0, l0);
        split2(v.y, h1, l1);
        __nv_bfloat162 hh; hh.x = h0; hh.y = h1;
        __nv_bfloat162 ll; ll.x = l0; ll.y = l1;
        *(__nv_bfloat162*)(g_xs2 + (size_t)b * Ddim + 2 * dp) = hh;
        *(__nv_bfloat162*)(g_xs2 + (size_t)(Bdim + b) * Ddim + 2 * dp) = ll;
        return;
    }

    int o = blockIdx.x - 1024;
    const float4* src = (const float4*)(betas + (size_t)o * Ddim * Ddim);
    float4* dst4 = (float4*)bsm;
#pragma unroll
    for (int i = 0; i < 4; i++) dst4[t + i * 256] = src[t + i * 256];
    if (t < Ddim) cs[t] = centers[o * Ddim + t];
    __syncthreads();
    {
        int e = t >> 2, dg = (t & 3) * 16;
        __nv_bfloat16* oh = g_bs2 + (size_t)o * 2 * Ddim * Ddim + (size_t)e * Ddim;
        __nv_bfloat16* ol = oh + Ddim * Ddim;
#pragma unroll
        for (int j = 0; j < 8; j++) {
            int d0 = dg + 2 * j;
            float v0 = bsm[d0 * Ddim + e];
            float v1 = bsm[(d0 + 1) * Ddim + e];
            __nv_bfloat16 h0, l0, h1, l1;
            split2(v0, h0, l0);
            split2(v1, h1, l1);
            __nv_bfloat162 hh; hh.x = h0; hh.y = h1;
            __nv_bfloat162 ll; ll.x = l0; ll.y = l1;
            *(__nv_bfloat162*)(oh + d0) = hh;
            *(__nv_bfloat162*)(ol + d0) = ll;
        }
    }
    if (t < Ddim) {
        float s = 0.f;
#pragma unroll 8
        for (int d = 0; d < Ddim; d++) s = fmaf(bsm[d * Ddim + t], cs[d], s);
        g_cproj[o * Ddim + t] = s;
    }
}

// ---------------- main kernel ----------------
#define XROW 144
#define MT 64                    // rows per b-tile
#define TPB 16                   // tiles per block
#define XBUF 9216                // 64 rows * 144
#define SM_X0 0                  // buf0: 2 splits * 9216 = 18432
#define SM_X1 18432
#define SM_BS 36864              // 2 splits * 128 n-rows * 144
#define SM_NCP 73728             // 128 floats
#define SM_PART 74240            // 2 * 256 floats (double-buffered)
#define SM_TOTAL 76288

__device__ __forceinline__ void stage_x(unsigned sb_buf, int b0, int tid) {
    const unsigned char* xg = (const unsigned char*)g_xs2;
#pragma unroll
    for (int i = 0; i < 8; i++) {
        int idx = tid + i * 128;
        int split = idx >> 9, row = (idx >> 3) & 63, c = idx & 7;
        unsigned dst = sb_buf + split * XBUF + row * XROW + c * 16;
        const unsigned char* src = xg + (size_t)split * (Bdim * Ddim * 2)
                                      + (size_t)(b0 + row) * (Ddim * 2) + c * 16;
        CP_ASYNC16(dst, src);
    }
    CP_COMMIT();
}

__global__ __launch_bounds__(128) void ebf_mma(float* __restrict__ out) {
    extern __shared__ __align__(16) unsigned char smem[];
    unsigned sb = smem_u32(smem);
    int tid = threadIdx.x;
    int lane = tid & 31, wid = tid >> 5;
    int o0 = blockIdx.x * 2;
    int bbase0 = blockIdx.y * (MT * TPB);

    // ---- stage beta o-pair: smem [split][n = ol*64 + e][144B rows] ----
    {
        const float4* src = (const float4*)(g_bs2 + (size_t)o0 * 2 * Ddim * Ddim);
#pragma unroll
        for (int i = 0; i < 16; i++) {
            int idx = tid + i * 128;           // 2048 float4
            int c = idx & 7, e = (idx >> 3) & 63, s = (idx >> 9) & 1, ol = idx >> 10;
            float4 v = src[(size_t)(ol * 2 + s) * 512 + e * 8 + c];
            *(float4*)(smem + SM_BS + s * 18432 + (ol * 64 + e) * XROW + c * 16) = v;
        }
    }
    ((float*)(smem + SM_NCP))[tid] = -g_cproj[(o0 + (tid >> 6)) * Ddim + (tid & 63)];

    stage_x(sb + SM_X0, bbase0, tid);
    stage_x(sb + SM_X1, bbase0 + MT, tid);
    __syncthreads();

    // ---- B fragments once per block: Breg[split][k][npair][4] (64 regs) ----
    int n0 = wid * 32;
    unsigned Breg[2][4][2][4];
#pragma unroll
    for (int s = 0; s < 2; s++)
#pragma unroll
        for (int k = 0; k < 4; k++)
#pragma unroll
            for (int np = 0; np < 2; np++) {
                unsigned addr = sb + SM_BS + s * 18432
                    + (n0 + (lane & 7) + ((lane >> 4) & 1) * 8 + np * 16) * XROW
                    + ((lane >> 3) & 1) * 16 + k * 32;
                ldsm4(Breg[s][k][np], addr);
            }

    const float* ncp = (const float*)(smem + SM_NCP);

    for (int j = 0; j < TPB; j++) {
        if (j < TPB - 1) { CP_WAIT1(); } else { CP_WAIT0(); }
        __syncthreads();                               // x-buf ready, prev part consumed
        unsigned xbuf = sb + ((j & 1) ? SM_X1 : SM_X0);

        float acc[4][4][4];   // [mi][ns][4]
#pragma unroll
        for (int ns = 0; ns < 4; ns++) {
            float2 v = *(const float2*)(ncp + n0 + ns * 8 + 2 * (lane & 3));
#pragma unroll
            for (int mi = 0; mi < 4; mi++) {
                acc[mi][ns][0] = v.x; acc[mi][ns][1] = v.y;
                acc[mi][ns][2] = v.x; acc[mi][ns][3] = v.y;
            }
        }

        unsigned abase = xbuf + (lane & 15) * XROW + (lane >> 4) * 16;
#pragma unroll
        for (int k = 0; k < 4; k++) {
#pragma unroll
            for (int mi = 0; mi < 4; mi++) {
                unsigned Ah[4], Al[4];
                ldsm4(Ah, abase + mi * 16 * XROW + k * 32);
                ldsm4(Al, abase + XBUF + mi * 16 * XROW + k * 32);
#pragma unroll
                for (int np = 0; np < 2; np++) {
                    mma16816(acc[mi][2 * np],     Ah, Breg[0][k][np]);
                    mma16816(acc[mi][2 * np + 1], Ah, Breg[0][k][np] + 2);
                    mma16816(acc[mi][2 * np],     Ah, Breg[1][k][np]);
                    mma16816(acc[mi][2 * np + 1], Ah, Breg[1][k][np] + 2);
                    mma16816(acc[mi][2 * np],     Al, Breg[0][k][np]);
                    mma16816(acc[mi][2 * np + 1], Al, Breg[0][k][np] + 2);
                }
            }
        }

        // ---- epilogue ----
        float* partb = (float*)(smem + SM_PART) + (j & 1) * 256;
#pragma unroll
        for (int mi = 0; mi < 4; mi++) {
            float qa = 0.f, qb = 0.f;
#pragma unroll
            for (int ns = 0; ns < 4; ns++) {
                qa = fmaf(acc[mi][ns][0], acc[mi][ns][0], qa);
                qa = fmaf(acc[mi][ns][1], acc[mi][ns][1], qa);
                qb = fmaf(acc[mi][ns][2], acc[mi][ns][2], qb);
                qb = fmaf(acc[mi][ns][3], acc[mi][ns][3], qb);
            }
            qa += __shfl_xor_sync(0xFFFFFFFFu, qa, 1);
            qa += __shfl_xor_sync(0xFFFFFFFFu, qa, 2);
            qb += __shfl_xor_sync(0xFFFFFFFFu, qb, 1);
            qb += __shfl_xor_sync(0xFFFFFFFFu, qb, 2);
            if ((lane & 3) == 0) {
                int r = lane >> 2;
                partb[wid * 64 + mi * 16 + r]     = qa;
                partb[wid * 64 + mi * 16 + r + 8] = qb;
            }
        }
        __syncthreads();                               // part written; all ldsm of buf done

        if (j + 2 < TPB)
            stage_x(sb + ((j & 1) ? SM_X1 : SM_X0), bbase0 + (j + 2) * MT, tid);

        int b0 = bbase0 + j * MT;
        if (tid < MT) {
            float s0 = partb[0 * 64 + tid] + partb[1 * 64 + tid];
            float s1 = partb[2 * 64 + tid] + partb[3 * 64 + tid];
            float2 r = make_float2(__expf(-s0), __expf(-s1));
            *(float2*)(out + (size_t)(b0 + tid) * Odim + o0) = r;
        }
        // no trailing sync: next iteration's top barrier protects part/x-buf reuse
    }
}

// ---------------- launch ----------------
extern "C" void kernel_launch(void* const* d_in, const int* in_sizes, int n_in,
                              void* d_out, int out_size) {
    const float* x       = (const float*)d_in[0];   // [8192, 64]
    const float* centers = (const float*)d_in[1];   // [256, 1, 64]
    const float* betas   = (const float*)d_in[2];   // [256, 64, 64]
    float* out = (float*)d_out;                     // [8192, 256]

    cudaFuncSetAttribute(ebf_mma, cudaFuncAttributeMaxDynamicSharedMemorySize, SM_TOTAL);

    prep_kernel<<<1280, 256>>>(x, betas, centers);
    dim3 grid(Odim / 2, Bdim / (MT * TPB));         // 128 x 8 = 1024 blocks
    ebf_mma<<<grid, 128, SM_TOTAL>>>(out);
}

// round 16
// speedup vs baseline: 1.5413x; 1.5413x over previous
#include <cuda_runtime.h>
#include <cuda_bf16.h>
#include <math.h>
#include <stdint.h>

#define Bdim 8192
#define Ddim 64
#define Odim 256

// ---------------- global scratch ----------------
__device__ __align__(16) __nv_bfloat16 g_xs2[2 * Bdim * Ddim];          // [split][b][d]
__device__ __align__(16) __nv_bfloat16 g_bs2[Odim * 2 * Ddim * Ddim];   // [o][split][e][d]
__device__ float g_cproj[Odim * Ddim];

// ---------------- helpers ----------------
__device__ __forceinline__ unsigned smem_u32(const void* p) {
    unsigned a;
    asm("{ .reg .u64 t; cvta.to.shared.u64 t, %1; cvt.u32.u64 %0, t; }" : "=r"(a) : "l"(p));
    return a;
}
__device__ __forceinline__ void split2(float a, __nv_bfloat16& h, __nv_bfloat16& l) {
    h = __float2bfloat16(a);
    l = __float2bfloat16(a - __bfloat162float(h));
}
__device__ __forceinline__ void ldsm4(unsigned* r, unsigned addr) {
    asm volatile("ldmatrix.sync.aligned.m8n8.x4.shared.b16 {%0,%1,%2,%3}, [%4];"
                 : "=r"(r[0]), "=r"(r[1]), "=r"(r[2]), "=r"(r[3]) : "r"(addr));
}
__device__ __forceinline__ void mma16816(float* c, const unsigned* a, const unsigned* b) {
    asm volatile("mma.sync.aligned.m16n8k16.row.col.f32.bf16.bf16.f32 "
                 "{%0,%1,%2,%3}, {%4,%5,%6,%7}, {%8,%9}, {%0,%1,%2,%3};"
                 : "+f"(c[0]), "+f"(c[1]), "+f"(c[2]), "+f"(c[3])
                 : "r"(a[0]), "r"(a[1]), "r"(a[2]), "r"(a[3]), "r"(b[0]), "r"(b[1]));
}
#define CP_ASYNC16(dst, src) \
    asm volatile("cp.async.cg.shared.global [%0], [%1], 16;" :: "r"(dst), "l"(src) : "memory")
#define CP_COMMIT() asm volatile("cp.async.commit_group;" ::: "memory")
#define CP_WAIT1()  asm volatile("cp.async.wait_group 1;" ::: "memory")
#define CP_WAIT0()  asm volatile("cp.async.wait_group 0;" ::: "memory")

// ---------------- merged prep kernel ----------------
// blocks [0, 1024): x split ; blocks [1024, 1280): beta split + cproj
__global__ __launch_bounds__(256) void prep_kernel(const float* __restrict__ x,
                                                   const float* __restrict__ betas,
                                                   const float* __restrict__ centers) {
    __shared__ float bsm[Ddim * Ddim];
    __shared__ float cs[Ddim];
    int t = threadIdx.x;

    if (blockIdx.x < 1024) {
        int idx = blockIdx.x * 256 + t;
        int b = idx >> 5, dp = idx & 31;
        float2 v = *(const float2*)(x + b * Ddim + 2 * dp);
        __nv_bfloat16 h0, l0, h1, l1;
        split2(v.x, h0, l0);
        split2(v.y, h1, l1);
        __nv_bfloat162 hh; hh.x = h0; hh.y = h1;
        __nv_bfloat162 ll; ll.x = l0; ll.y = l1;
        *(__nv_bfloat162*)(g_xs2 + (size_t)b * Ddim + 2 * dp) = hh;
        *(__nv_bfloat162*)(g_xs2 + (size_t)(Bdim + b) * Ddim + 2 * dp) = ll;
        return;
    }

    int o = blockIdx.x - 1024;
    const float4* src = (const float4*)(betas + (size_t)o * Ddim * Ddim);
    float4* dst4 = (float4*)bsm;
#pragma unroll
    for (int i = 0; i < 4; i++) dst4[t + i * 256] = src[t + i * 256];
    if (t < Ddim) cs[t] = centers[o * Ddim + t];
    __syncthreads();
    {
        int e = t >> 2, dg = (t & 3) * 16;
        __nv_bfloat16* oh = g_bs2 + (size_t)o * 2 * Ddim * Ddim + (size_t)e * Ddim;
        __nv_bfloat16* ol = oh + Ddim * Ddim;
#pragma unroll
        for (int j = 0; j < 8; j++) {
            int d0 = dg + 2 * j;
            float v0 = bsm[d0 * Ddim + e];
            float v1 = bsm[(d0 + 1) * Ddim + e];
            __nv_bfloat16 h0, l0, h1, l1;
            split2(v0, h0, l0);
            split2(v1, h1, l1);
            __nv_bfloat162 hh; hh.x = h0; hh.y = h1;
            __nv_bfloat162 ll; ll.x = l0; ll.y = l1;
            *(__nv_bfloat162*)(oh + d0) = hh;
            *(__nv_bfloat162*)(ol + d0) = ll;
        }
    }
    if (t < Ddim) {
        float s = 0.f;
#pragma unroll 8
        for (int d = 0; d < Ddim; d++) s = fmaf(bsm[d * Ddim + t], cs[d], s);
        g_cproj[o * Ddim + t] = s;
    }
}

// ---------------- main kernel ----------------
#define XROW 144
#define MT 64                    // rows per b-tile
#define TPB 8                    // tiles per block
#define XBUF 9216                // 64 rows * 144
#define SM_X0 0                  // buf0: 2 splits * 9216 = 18432
#define SM_X1 18432
#define SM_BS 36864              // 2 splits * 128 n-rows * 144
#define SM_NCP 73728             // 128 floats
#define SM_PART 74240            // 8 * 64 floats
#define SM_TOTAL 76288

__device__ __forceinline__ void stage_x(unsigned sb_buf, int b0, int tid) {
    // only tids 0-127 issue; others' commit/wait are trivially satisfied
    if (tid < 128) {
        const unsigned char* xg = (const unsigned char*)g_xs2;
#pragma unroll
        for (int i = 0; i < 8; i++) {
            int idx = tid + i * 128;
            int split = idx >> 9, row = (idx >> 3) & 63, c = idx & 7;
            unsigned dst = sb_buf + split * XBUF + row * XROW + c * 16;
            const unsigned char* src = xg + (size_t)split * (Bdim * Ddim * 2)
                                          + (size_t)(b0 + row) * (Ddim * 2) + c * 16;
            CP_ASYNC16(dst, src);
        }
    }
    CP_COMMIT();
}

__global__ __launch_bounds__(256, 2) void ebf_mma(float* __restrict__ out) {
    extern __shared__ __align__(16) unsigned char smem[];
    unsigned sb = smem_u32(smem);
    int tid = threadIdx.x;
    int lane = tid & 31, wid = tid >> 5;     // 8 warps
    int o0 = blockIdx.x * 2;
    int bbase0 = blockIdx.y * (MT * TPB);

    // ---- stage beta o-pair: smem [split][n = ol*64 + e][144B rows] ----
    {
        const float4* src = (const float4*)(g_bs2 + (size_t)o0 * 2 * Ddim * Ddim);
#pragma unroll
        for (int i = 0; i < 8; i++) {
            int idx = tid + i * 256;           // 2048 float4
            int c = idx & 7, e = (idx >> 3) & 63, s = (idx >> 9) & 1, ol = idx >> 10;
            float4 v = src[(size_t)(ol * 2 + s) * 512 + e * 8 + c];
            *(float4*)(smem + SM_BS + s * 18432 + (ol * 64 + e) * XROW + c * 16) = v;
        }
    }
    if (tid < 128)
        ((float*)(smem + SM_NCP))[tid] = -g_cproj[(o0 + (tid >> 6)) * Ddim + (tid & 63)];

    stage_x(sb + SM_X0, bbase0, tid);
    stage_x(sb + SM_X1, bbase0 + MT, tid);
    __syncthreads();

    // ---- B fragments once per block: warp covers n=16 -> Breg[split][k][4] (32 regs) ----
    int n0 = wid * 16;
    unsigned Breg[2][4][4];
#pragma unroll
    for (int s = 0; s < 2; s++)
#pragma unroll
        for (int k = 0; k < 4; k++) {
            unsigned addr = sb + SM_BS + s * 18432
                + (n0 + (lane & 7) + ((lane >> 4) & 1) * 8) * XROW
                + ((lane >> 3) & 1) * 16 + k * 32;
            ldsm4(Breg[s][k], addr);
        }

    const float* ncp = (const float*)(smem + SM_NCP);
    float* part = (float*)(smem + SM_PART);

    for (int j = 0; j < TPB; j++) {
        if (j < TPB - 1) { CP_WAIT1(); } else { CP_WAIT0(); }
        __syncthreads();
        unsigned xbuf = sb + ((j & 1) ? SM_X1 : SM_X0);

        // ---- init acc to -cproj: acc[mi][ns][4], warp's 16 n's ----
        float acc[4][2][4];
        {
            float2 v0 = *(const float2*)(ncp + n0 + 2 * (lane & 3));
            float2 v1 = *(const float2*)(ncp + n0 + 8 + 2 * (lane & 3));
#pragma unroll
            for (int mi = 0; mi < 4; mi++) {
                acc[mi][0][0] = v0.x; acc[mi][0][1] = v0.y;
                acc[mi][0][2] = v0.x; acc[mi][0][3] = v0.y;
                acc[mi][1][0] = v1.x; acc[mi][1][1] = v1.y;
                acc[mi][1][2] = v1.x; acc[mi][1][3] = v1.y;
            }
        }

        unsigned abase = xbuf + (lane & 15) * XROW + (lane >> 4) * 16;
#pragma unroll
        for (int k = 0; k < 4; k++) {
#pragma unroll
            for (int mi = 0; mi < 4; mi++) {
                unsigned Ah[4], Al[4];
                ldsm4(Ah, abase + mi * 16 * XROW + k * 32);
                ldsm4(Al, abase + XBUF + mi * 16 * XROW + k * 32);
                // 3 split-products into 2 independent acc chains
                mma16816(acc[mi][0], Ah, Breg[0][k]);
                mma16816(acc[mi][1], Ah, Breg[0][k] + 2);
                mma16816(acc[mi][0], Ah, Breg[1][k]);
                mma16816(acc[mi][1], Ah, Breg[1][k] + 2);
                mma16816(acc[mi][0], Al, Breg[0][k]);
                mma16816(acc[mi][1], Al, Breg[0][k] + 2);
            }
        }

        // ---- epilogue: sum of squares over this warp's 16 e's ----
#pragma unroll
        for (int mi = 0; mi < 4; mi++) {
            float qa = 0.f, qb = 0.f;
#pragma unroll
            for (int ns = 0; ns < 2; ns++) {
                qa = fmaf(acc[mi][ns][0], acc[mi][ns][0], qa);
                qa = fmaf(acc[mi][ns][1], acc[mi][ns][1], qa);
                qb = fmaf(acc[mi][ns][2], acc[mi][ns][2], qb);
                qb = fmaf(acc[mi][ns][3], acc[mi][ns][3], qb);
            }
            qa += __shfl_xor_sync(0xFFFFFFFFu, qa, 1);
            qa += __shfl_xor_sync(0xFFFFFFFFu, qa, 2);
            qb += __shfl_xor_sync(0xFFFFFFFFu, qb, 1);
            qb += __shfl_xor_sync(0xFFFFFFFFu, qb, 2);
            if ((lane & 3) == 0) {
                int r = lane >> 2;
                part[wid * 64 + mi * 16 + r]     = qa;
                part[wid * 64 + mi * 16 + r + 8] = qb;
            }
        }
        __syncthreads();

        int b0 = bbase0 + j * MT;
        if (tid < MT) {
            float s0 = part[0 * 64 + tid] + part[1 * 64 + tid]
                     + part[2 * 64 + tid] + part[3 * 64 + tid];
            float s1 = part[4 * 64 + tid] + part[5 * 64 + tid]
                     + part[6 * 64 + tid] + part[7 * 64 + tid];
            float2 r = make_float2(__expf(-s0), __expf(-s1));
            *(float2*)(out + (size_t)(b0 + tid) * Odim + o0) = r;
        }
        __syncthreads();   // part consumed + all ldsm of this x-buf done

        if (j + 2 < TPB)
            stage_x(sb + ((j & 1) ? SM_X1 : SM_X0), bbase0 + (j + 2) * MT, tid);
    }
}

// ---------------- launch ----------------
extern "C" void kernel_launch(void* const* d_in, const int* in_sizes, int n_in,
                              void* d_out, int out_size) {
    const float* x       = (const float*)d_in[0];   // [8192, 64]
    const float* centers = (const float*)d_in[1];   // [256, 1, 64]
    const float* betas   = (const float*)d_in[2];   // [256, 64, 64]
    float* out = (float*)d_out;                     // [8192, 256]

    cudaFuncSetAttribute(ebf_mma, cudaFuncAttributeMaxDynamicSharedMemorySize, SM_TOTAL);

    prep_kernel<<<1280, 256>>>(x, betas, centers);
    dim3 grid(Odim / 2, Bdim / (MT * TPB));         // 128 x 16 = 2048 blocks
    ebf_mma<<<grid, 256, SM_TOTAL>>>(out);
}